// round 2
// baseline (speedup 1.0000x reference)
#include <cuda_runtime.h>

// Problem constants (fixed by setup_inputs)
#define BATCH 1024
#define TLEN  512
#define NTAGS 64
#define START_TAG 62
#define STOP_TAG  63

// Scratch (no cudaMalloc allowed)
__device__ float g_logZ[BATCH];
__device__ float g_gold[BATCH];
__device__ int   g_tags_is64;

#define BPC 8  // batches per CTA in forward kernel

// ---------------------------------------------------------------------------
// Detect tags dtype at runtime (JAX may silently downcast int64 -> int32).
// If int64 (little-endian), every odd 32-bit word of the first 512 elements
// is 0 (tags in [0,62)). If int32, odd words are random tags (~0 chance all 0).
// ---------------------------------------------------------------------------
__global__ void crf_detect_kernel(const int* __restrict__ tags32)
{
    const int tid = threadIdx.x;
    int v = 0;
    for (int i = tid; i < 512; i += 32)
        v |= tags32[2 * i + 1];
#pragma unroll
    for (int off = 16; off; off >>= 1)
        v |= __shfl_xor_sync(0xffffffffu, v, off);
    if (tid == 0) g_tags_is64 = (v == 0) ? 1 : 0;
}

// ---------------------------------------------------------------------------
// Forward (log-partition) kernel.
// grid = BATCH/BPC = 128 CTAs, block = 128 threads.
// thread (j = tid&63, g = tid>>6) owns column j for batches b0+g*4 .. b0+g*4+3.
// E[:,j] = exp(trans[:,j]) lives in 64 registers per thread.
// Recursion in scaled linear space: alpha = s + ln(p); renorm every 4 steps.
// ---------------------------------------------------------------------------
__global__ __launch_bounds__(128, 2)
void crf_forward_kernel(const float* __restrict__ em,
                        const float* __restrict__ trans,
                        const int*   __restrict__ mask)
{
    __shared__ float P_sh[NTAGS][BPC];   // p values, [i][batch-in-cta]
    __shared__ float Red[4][4];          // per-warp reduction partials

    const int tid  = threadIdx.x;
    const int j    = tid & 63;
    const int g    = tid >> 6;           // batch half 0/1
    const int warp = tid >> 5;           // 0..3
    const int lane = tid & 31;
    const int b0   = blockIdx.x * BPC + g * 4;

    // E column j in registers (exp(-10000) -> 0 exactly: forbidden transitions vanish)
    float Ecol[NTAGS];
#pragma unroll
    for (int i = 0; i < NTAGS; i++)
        Ecol[i] = expf(trans[i * NTAGS + j]);
    const float Estop = expf(trans[j * NTAGS + STOP_TAG]);

    const float LOG2E = 1.4426950408889634f;

    float p[4], s[4];
#pragma unroll
    for (int k = 0; k < 4; k++) { p[k] = (j == START_TAG) ? 1.0f : 0.0f; s[k] = 0.0f; }

    // prefetch emissions for t = 0
    float ecur[4];
#pragma unroll
    for (int k = 0; k < 4; k++)
        ecur[k] = em[(size_t)(b0 + k) * TLEN * NTAGS + j];

    for (int t = 0; t < TLEN; ++t) {
        // ---- renormalize every 4 steps (identity transform: alpha unchanged) ----
        if ((t & 3) == 0 && t) {
            float mx[4];
#pragma unroll
            for (int k = 0; k < 4; k++) {
                float v = p[k];
#pragma unroll
                for (int off = 16; off; off >>= 1)
                    v = fmaxf(v, __shfl_xor_sync(0xffffffffu, v, off));
                mx[k] = v;
            }
            if (lane == 0) {
#pragma unroll
                for (int k = 0; k < 4; k++) Red[warp][k] = mx[k];
            }
            __syncthreads();
#pragma unroll
            for (int k = 0; k < 4; k++) {
                float m = fmaxf(Red[2 * g][k], Red[2 * g + 1][k]);
                float inv = 1.0f / m;
                p[k] *= inv;
                s[k] += logf(m);
            }
            // Red is not rewritten before the next __syncthreads below -> safe.
        }

        // ---- publish p ----
        *(float4*)&P_sh[j][g * 4] = make_float4(p[0], p[1], p[2], p[3]);
        __syncthreads();

        // ---- prefetch next-step emissions (hide DRAM behind FMA body) ----
        float enext[4];
#pragma unroll
        for (int k = 0; k < 4; k++) enext[k] = ecur[k];
        if (t + 1 < TLEN) {
#pragma unroll
            for (int k = 0; k < 4; k++)
                enext[k] = em[(size_t)(b0 + k) * TLEN * NTAGS + (size_t)(t + 1) * NTAGS + j];
        }
        int mk[4];
#pragma unroll
        for (int k = 0; k < 4; k++)
            mk[k] = mask[(size_t)(b0 + k) * TLEN + t];

        // ---- q[b] = sum_i p[b][i] * E[i][j]  (the FMA-bound core) ----
        float q0 = 0.f, q1 = 0.f, q2 = 0.f, q3 = 0.f;
#pragma unroll
        for (int i = 0; i < NTAGS; i++) {
            float4 pv = *(const float4*)&P_sh[i][g * 4];   // broadcast LDS.128
            q0 = fmaf(pv.x, Ecol[i], q0);
            q1 = fmaf(pv.y, Ecol[i], q1);
            q2 = fmaf(pv.z, Ecol[i], q2);
            q3 = fmaf(pv.w, Ecol[i], q3);
        }
        __syncthreads();   // P_sh free for next step

        float qq[4] = {q0, q1, q2, q3};
#pragma unroll
        for (int k = 0; k < 4; k++) {
            float pn = qq[k] * exp2f(ecur[k] * LOG2E);
            p[k] = mk[k] ? pn : p[k];   // masked step keeps alpha
            ecur[k] = enext[k];
        }
    }

    // ---- epilogue: logZ[b] = s + ln( sum_j p[b][j] * exp(trans[j][STOP]) ) ----
    float v[4];
#pragma unroll
    for (int k = 0; k < 4; k++) {
        float x = p[k] * Estop;
#pragma unroll
        for (int off = 16; off; off >>= 1)
            x += __shfl_xor_sync(0xffffffffu, x, off);
        v[k] = x;
    }
    if (lane == 0) {
#pragma unroll
        for (int k = 0; k < 4; k++) Red[warp][k] = v[k];
    }
    __syncthreads();
    if ((tid & 63) == 0) {
#pragma unroll
        for (int k = 0; k < 4; k++) {
            float sum = Red[2 * g][k] + Red[2 * g + 1][k];
            g_logZ[b0 + k] = s[k] + logf(sum);
        }
    }
}

// ---------------------------------------------------------------------------
// Gold-score kernel: one warp per batch; warp-scan for "last valid previous tag".
// Dtype-agnostic tags load (int32 vs int64, flag from crf_detect_kernel).
// ---------------------------------------------------------------------------
__global__ void crf_gold_kernel(const float* __restrict__ em,
                                const float* __restrict__ trans,
                                const void* __restrict__ tags_raw,
                                const int* __restrict__ mask)
{
    const int gw   = (blockIdx.x * blockDim.x + threadIdx.x) >> 5;
    const int lane = threadIdx.x & 31;
    if (gw >= BATCH) return;
    const int b = gw;
    const int is64 = g_tags_is64;
    const long long* tags64 = (const long long*)tags_raw;
    const int*       tags32 = (const int*)tags_raw;

    float acc = 0.0f;
    int carry = START_TAG;

    for (int base = 0; base < TLEN; base += 32) {
        const int t   = base + lane;
        const size_t idx = (size_t)b * TLEN + t;
        const int tag = is64 ? (int)tags64[idx] : tags32[idx];
        const int m   = mask[idx];
        const float e = em[(size_t)b * TLEN * NTAGS + (size_t)t * NTAGS + tag];

        int inc = m ? tag : -1;                 // inclusive "last valid tag" scan
#pragma unroll
        for (int off = 1; off < 32; off <<= 1) {
            int o = __shfl_up_sync(0xffffffffu, inc, off);
            if (lane >= off && inc < 0) inc = o;
        }
        int prevv = __shfl_up_sync(0xffffffffu, inc, 1);
        int prev  = (lane == 0 || prevv < 0) ? carry : prevv;

        if (m) acc += e + trans[prev * NTAGS + tag];

        int last = __shfl_sync(0xffffffffu, inc, 31);
        if (last >= 0) carry = last;
    }
#pragma unroll
    for (int off = 16; off; off >>= 1)
        acc += __shfl_xor_sync(0xffffffffu, acc, off);
    if (lane == 0)
        g_gold[b] = acc + trans[carry * NTAGS + STOP_TAG];
}

// ---------------------------------------------------------------------------
// Final reduction: mean(logZ - gold) -> d_out[0]
// ---------------------------------------------------------------------------
__global__ void crf_reduce_kernel(float* __restrict__ out)
{
    __shared__ float sh[256];
    const int tid = threadIdx.x;
    float a = 0.0f;
    for (int i = tid; i < BATCH; i += 256)
        a += g_logZ[i] - g_gold[i];
    sh[tid] = a;
    __syncthreads();
    for (int s = 128; s; s >>= 1) {
        if (tid < s) sh[tid] += sh[tid + s];
        __syncthreads();
    }
    if (tid == 0) out[0] = sh[0] / (float)BATCH;
}

// ---------------------------------------------------------------------------
extern "C" void kernel_launch(void* const* d_in, const int* in_sizes, int n_in,
                              void* d_out, int out_size)
{
    const float* em    = (const float*)d_in[0];   // (1024, 512, 64) f32
    const float* trans = (const float*)d_in[1];   // (64, 64) f32
    const void*  tags  = d_in[2];                 // (1024, 512) i32 or i64
    const int*   mask  = (const int*)d_in[3];     // (1024, 512) i32
    float* out = (float*)d_out;

    crf_detect_kernel<<<1, 32>>>((const int*)tags);
    crf_gold_kernel<<<BATCH / 8, 256>>>(em, trans, tags, mask);
    crf_forward_kernel<<<BATCH / BPC, 128>>>(em, trans, mask);
    crf_reduce_kernel<<<1, 256>>>(out);
}

// round 5
// speedup vs baseline: 1.2389x; 1.2389x over previous
#include <cuda_runtime.h>

// Problem constants (fixed by setup_inputs)
#define BATCH 1024
#define TLEN  512
#define NTAGS 64
#define START_TAG 62
#define STOP_TAG  63
#define BPC 8   // batches per CTA

// Scratch (no cudaMalloc allowed)
__device__ float g_logZ[BATCH];
__device__ float g_gold[BATCH];
__device__ int   g_tags_is64;

// ---------------------------------------------------------------------------
// Detect tags dtype at runtime (JAX silently downcasts int64 -> int32).
// int64 little-endian: odd 32-bit words of first 512 elems are all 0.
// ---------------------------------------------------------------------------
__global__ void crf_detect_kernel(const int* __restrict__ tags32)
{
    const int tid = threadIdx.x;
    int v = 0;
    for (int i = tid; i < 512; i += 32)
        v |= tags32[2 * i + 1];
#pragma unroll
    for (int off = 16; off; off >>= 1)
        v |= __shfl_xor_sync(0xffffffffu, v, off);
    if (tid == 0) g_tags_is64 = (v == 0) ? 1 : 0;
}

// ---------------------------------------------------------------------------
// Forward (log-partition) kernel.
// grid = 128 CTAs x 256 threads (8 warps -> 2 warps/SMSP).
// thread (j = tid&63, g = tid>>6) owns column j for local batches 2g, 2g+1.
// E[:,j] in 64 registers. Scalar FFMA inner product (f32x2 path kills the
// toolchain -- see R3/R4). Scaled-linear recursion, renorm every 8 steps,
// double-buffered P_sh (one __syncthreads per step), mask staged in smem.
// ---------------------------------------------------------------------------
__global__ __launch_bounds__(256, 1)
void crf_forward_kernel(const float* __restrict__ em,
                        const float* __restrict__ trans,
                        const int*   __restrict__ mask)
{
    __shared__ __align__(16) float P_sh[2][BPC][NTAGS]; // double-buffered p
    __shared__ __align__(16) int   M_sh[BPC][TLEN];     // staged mask
    __shared__ float Red[8][2];                         // per-warp partials

    const int tid  = threadIdx.x;
    const int j    = tid & 63;
    const int g    = tid >> 6;           // 0..3
    const int warp = tid >> 5;           // 0..7 (warp pairs 2g,2g+1 share g)
    const int lane = tid & 31;
    const int lA   = 2 * g, lB = 2 * g + 1;       // local batch rows
    const int bA   = blockIdx.x * BPC + lA;       // global batch

    // stage mask into smem (vectorized, coalesced)
    {
        const int4* msrc = (const int4*)(mask + (size_t)blockIdx.x * BPC * TLEN);
        int4*       mdst = (int4*)&M_sh[0][0];
        for (int idx = tid; idx < BPC * TLEN / 4; idx += 256)
            mdst[idx] = msrc[idx];
    }

    // E column j in registers (exp(-10000) -> 0: forbidden transitions vanish)
    float Ecol[NTAGS];
#pragma unroll
    for (int i = 0; i < NTAGS; i++)
        Ecol[i] = expf(trans[i * NTAGS + j]);
    const float Estop = expf(trans[j * NTAGS + STOP_TAG]);

    float p0 = (j == START_TAG) ? 1.0f : 0.0f, p1 = p0;
    float s0 = 0.0f, s1 = 0.0f;

    const size_t strideB = (size_t)TLEN * NTAGS;
    const float* emA = em + (size_t)bA * strideB + j;
    const float* emB = emA + strideB;
    float eA = emA[0], eB = emB[0];              // prefetch t=0

    __syncthreads();                              // mask staged

    for (int t = 0; t < TLEN; ++t) {
        // ---- renormalize every 8 steps (growth <= 2^14.4/step -> 2^115 < fp32 max) ----
        if ((t & 7) == 0 && t) {
            float m0 = p0, m1 = p1;
#pragma unroll
            for (int off = 16; off; off >>= 1) {
                m0 = fmaxf(m0, __shfl_xor_sync(0xffffffffu, m0, off));
                m1 = fmaxf(m1, __shfl_xor_sync(0xffffffffu, m1, off));
            }
            if (lane == 0) { Red[warp][0] = m0; Red[warp][1] = m1; }
            __syncthreads();
            float M0 = fmaxf(Red[warp & 6][0], Red[warp | 1][0]);
            float M1 = fmaxf(Red[warp & 6][1], Red[warp | 1][1]);
            p0 *= (1.0f / M0);  s0 += logf(M0);
            p1 *= (1.0f / M1);  s1 += logf(M1);
            // Red reads complete before its next write (8 publish-barriers away).
        }

        // ---- publish p (double buffer -> single barrier per step) ----
        const int buf = t & 1;
        P_sh[buf][lA][j] = p0;
        P_sh[buf][lB][j] = p1;
        __syncthreads();

        // ---- prefetch next emissions, read staged mask ----
        float eAn = eA, eBn = eB;
        if (t + 1 < TLEN) {
            const size_t off = (size_t)(t + 1) * NTAGS;
            eAn = emA[off];
            eBn = emB[off];
        }
        const int mA = M_sh[lA][t], mB = M_sh[lB][t];

        // ---- inner product: q[b] = sum_i p[b][i] * E[i][j]  (FFMA core) ----
        float q0 = 0.f, q1 = 0.f;
        const float* Pa = P_sh[buf][lA];
        const float* Pb = P_sh[buf][lB];
#pragma unroll
        for (int i4 = 0; i4 < 16; i4++) {
            float4 pa = *(const float4*)(Pa + 4 * i4);  // broadcast LDS.128
            float4 pb = *(const float4*)(Pb + 4 * i4);
            q0 = fmaf(pa.x, Ecol[4 * i4],     q0);
            q1 = fmaf(pb.x, Ecol[4 * i4],     q1);
            q0 = fmaf(pa.y, Ecol[4 * i4 + 1], q0);
            q1 = fmaf(pb.y, Ecol[4 * i4 + 1], q1);
            q0 = fmaf(pa.z, Ecol[4 * i4 + 2], q0);
            q1 = fmaf(pb.z, Ecol[4 * i4 + 2], q1);
            q0 = fmaf(pa.w, Ecol[4 * i4 + 3], q0);
            q1 = fmaf(pb.w, Ecol[4 * i4 + 3], q1);
        }
        float pn0 = q0 * __expf(eA);
        float pn1 = q1 * __expf(eB);
        p0 = mA ? pn0 : p0;      // masked step keeps alpha
        p1 = mB ? pn1 : p1;
        eA = eAn; eB = eBn;
    }

    // ---- epilogue: logZ[b] = s + ln( sum_j p[b][j] * Estop[j] ) ----
    float v0 = p0 * Estop, v1 = p1 * Estop;
#pragma unroll
    for (int off = 16; off; off >>= 1) {
        v0 += __shfl_xor_sync(0xffffffffu, v0, off);
        v1 += __shfl_xor_sync(0xffffffffu, v1, off);
    }
    if (lane == 0) { Red[warp][0] = v0; Red[warp][1] = v1; }
    __syncthreads();
    if ((tid & 63) == 0) {
        g_logZ[bA]     = s0 + logf(Red[warp][0] + Red[warp | 1][0]);
        g_logZ[bA + 1] = s1 + logf(Red[warp][1] + Red[warp | 1][1]);
    }
}

// ---------------------------------------------------------------------------
// Gold-score kernel: one warp per batch; warp-scan for "last valid prev tag".
// Dtype-agnostic tags load (int32 vs int64).
// ---------------------------------------------------------------------------
__global__ void crf_gold_kernel(const float* __restrict__ em,
                                const float* __restrict__ trans,
                                const void* __restrict__ tags_raw,
                                const int* __restrict__ mask)
{
    const int gw   = (blockIdx.x * blockDim.x + threadIdx.x) >> 5;
    const int lane = threadIdx.x & 31;
    if (gw >= BATCH) return;
    const int b = gw;
    const int is64 = g_tags_is64;
    const long long* tags64 = (const long long*)tags_raw;
    const int*       tags32 = (const int*)tags_raw;

    float acc = 0.0f;
    int carry = START_TAG;

    for (int base = 0; base < TLEN; base += 32) {
        const int t = base + lane;
        const size_t idx = (size_t)b * TLEN + t;
        const int tag = is64 ? (int)tags64[idx] : tags32[idx];
        const int m   = mask[idx];
        const float e = em[(size_t)b * TLEN * NTAGS + (size_t)t * NTAGS + tag];

        int inc = m ? tag : -1;                 // inclusive "last valid tag" scan
#pragma unroll
        for (int off = 1; off < 32; off <<= 1) {
            int o = __shfl_up_sync(0xffffffffu, inc, off);
            if (lane >= off && inc < 0) inc = o;
        }
        int prevv = __shfl_up_sync(0xffffffffu, inc, 1);
        int prev  = (lane == 0 || prevv < 0) ? carry : prevv;

        if (m) acc += e + trans[prev * NTAGS + tag];

        int last = __shfl_sync(0xffffffffu, inc, 31);
        if (last >= 0) carry = last;
    }
#pragma unroll
    for (int off = 16; off; off >>= 1)
        acc += __shfl_xor_sync(0xffffffffu, acc, off);
    if (lane == 0)
        g_gold[b] = acc + trans[carry * NTAGS + STOP_TAG];
}

// ---------------------------------------------------------------------------
// Final reduction: mean(logZ - gold) -> d_out[0]
// ---------------------------------------------------------------------------
__global__ void crf_reduce_kernel(float* __restrict__ out)
{
    __shared__ float sh[256];
    const int tid = threadIdx.x;
    float a = 0.0f;
    for (int i = tid; i < BATCH; i += 256)
        a += g_logZ[i] - g_gold[i];
    sh[tid] = a;
    __syncthreads();
    for (int s = 128; s; s >>= 1) {
        if (tid < s) sh[tid] += sh[tid + s];
        __syncthreads();
    }
    if (tid == 0) out[0] = sh[0] / (float)BATCH;
}

// ---------------------------------------------------------------------------
extern "C" void kernel_launch(void* const* d_in, const int* in_sizes, int n_in,
                              void* d_out, int out_size)
{
    const float* em    = (const float*)d_in[0];   // (1024, 512, 64) f32
    const float* trans = (const float*)d_in[1];   // (64, 64) f32
    const void*  tags  = d_in[2];                 // (1024, 512) i32 or i64
    const int*   mask  = (const int*)d_in[3];     // (1024, 512) i32
    float* out = (float*)d_out;

    crf_detect_kernel<<<1, 32>>>((const int*)tags);
    crf_gold_kernel<<<BATCH / 8, 256>>>(em, trans, tags, mask);
    crf_forward_kernel<<<BATCH / BPC, 256>>>(em, trans, mask);
    crf_reduce_kernel<<<1, 256>>>(out);
}